// round 3
// baseline (speedup 1.0000x reference)
#include <cuda_runtime.h>
#include <cstddef>

// Problem constants
#define BATCH 8
#define LEN   4096
#define IND   512
#define ST    256
#define OUTD  512

#define CHUNK 32
#define NCH   (LEN / CHUNK)   // 128

typedef unsigned long long ull;

// Scratch in device globals (no allocation allowed)
__device__ float g_uB[(size_t)BATCH * LEN * ST];      // 32 MB
__device__ float g_x [(size_t)BATCH * LEN * ST];      // 32 MB
__device__ float g_carry[BATCH * NCH * ST];
__device__ float g_init [BATCH * NCH * ST];

// Packed dual-fp32 FMA (Blackwell FFMA2): d = a*b + d elementwise on f32x2
#define FMA_F32X2(d, a, b) \
    asm("fma.rn.f32x2 %0, %1, %2, %0;" : "+l"(d) : "l"(a), "l"(b))

// ---------------------------------------------------------------------------
// Tiled fp32 GEMM using packed f32x2 FMA.
// Cm[M,N] = A[M,K] @ Bm[K,N], row-major. 128x128x16 tile, 256 threads,
// 8x8 microtile held as 8x4 f32x2 pairs. A values duplicated in smem so the
// broadcast multiplicand loads directly as a b64 pair (no per-k packing).
// ---------------------------------------------------------------------------
#define GBM 128
#define GBN 128
#define GBK 16

__global__ __launch_bounds__(256)
void gemm128(const float* __restrict__ A, const float* __restrict__ Bm,
             float* __restrict__ Cm, int M, int N, int K) {
    __shared__ float As2[2][GBK][2 * GBM];  // duplicated A: 32 KB
    __shared__ float Bs [2][GBK][GBN];      // 16 KB

    const int tid = threadIdx.x;
    const int rowBase = blockIdx.y * GBM;
    const int colBase = blockIdx.x * GBN;

    // A load: 128 rows x 16 cols; each thread 2 float4 along K (rows r, r+64)
    const int aRow = tid >> 2;           // 0..63
    const int aCol = (tid & 3) * 4;      // 0,4,8,12
    // B load: 16 rows x 128 cols; each thread 2 float4 along N (rows r, r+8)
    const int bRow = tid >> 5;           // 0..7
    const int bCol = (tid & 31) * 4;     // 0..124

    const int tm = (tid >> 4) * 8;       // 0..120
    const int tn = (tid & 15) * 8;       // 0..120

    ull acc[8][4] = {};

    // prologue: tile 0 -> buffer 0
    {
        const float* Ag = A + (size_t)(rowBase + aRow) * K + aCol;
        float4 a0 = *(const float4*)Ag;
        float4 a1 = *(const float4*)(Ag + (size_t)64 * K);
        #pragma unroll
        for (int i = 0; i < 4; i++) {
            float v0 = ((const float*)&a0)[i];
            float v1 = ((const float*)&a1)[i];
            *(float2*)&As2[0][aCol + i][2 * aRow]        = make_float2(v0, v0);
            *(float2*)&As2[0][aCol + i][2 * (aRow + 64)] = make_float2(v1, v1);
        }
        const float* Bg = Bm + (size_t)bRow * N + colBase + bCol;
        *(float4*)&Bs[0][bRow][bCol]     = *(const float4*)Bg;
        *(float4*)&Bs[0][bRow + 8][bCol] = *(const float4*)(Bg + (size_t)8 * N);
    }
    __syncthreads();

    const int nk = K / GBK;
    for (int kt = 0; kt < nk; kt++) {
        const int cur = kt & 1;
        const int nxt = cur ^ 1;
        float4 pa0, pa1, pb0, pb1;
        const bool havenext = (kt + 1 < nk);
        if (havenext) {
            const int k0 = (kt + 1) * GBK;
            const float* Ag = A + (size_t)(rowBase + aRow) * K + k0 + aCol;
            pa0 = *(const float4*)Ag;
            pa1 = *(const float4*)(Ag + (size_t)64 * K);
            const float* Bg = Bm + (size_t)(k0 + bRow) * N + colBase + bCol;
            pb0 = *(const float4*)Bg;
            pb1 = *(const float4*)(Bg + (size_t)8 * N);
        }

        #pragma unroll
        for (int k = 0; k < GBK; k++) {
            const ulonglong2* pA = (const ulonglong2*)&As2[cur][k][2 * tm];
            ulonglong2 A0 = pA[0], A1 = pA[1], A2 = pA[2], A3 = pA[3];
            ull a2[8] = {A0.x, A0.y, A1.x, A1.y, A2.x, A2.y, A3.x, A3.y};
            const ulonglong2* pB = (const ulonglong2*)&Bs[cur][k][tn];
            ulonglong2 B0 = pB[0], B1 = pB[1];
            ull b2[4] = {B0.x, B0.y, B1.x, B1.y};
            #pragma unroll
            for (int i = 0; i < 8; i++)
                #pragma unroll
                for (int j = 0; j < 4; j++)
                    FMA_F32X2(acc[i][j], a2[i], b2[j]);
        }

        if (havenext) {
            #pragma unroll
            for (int i = 0; i < 4; i++) {
                float v0 = ((const float*)&pa0)[i];
                float v1 = ((const float*)&pa1)[i];
                *(float2*)&As2[nxt][aCol + i][2 * aRow]        = make_float2(v0, v0);
                *(float2*)&As2[nxt][aCol + i][2 * (aRow + 64)] = make_float2(v1, v1);
            }
            *(float4*)&Bs[nxt][bRow][bCol]     = pb0;
            *(float4*)&Bs[nxt][bRow + 8][bCol] = pb1;
        }
        __syncthreads();
    }

    #pragma unroll
    for (int i = 0; i < 8; i++) {
        float* Cp = &Cm[(size_t)(rowBase + tm + i) * N + colBase + tn];
        ulonglong2 v0; v0.x = acc[i][0]; v0.y = acc[i][1];
        ulonglong2 v1; v1.x = acc[i][2]; v1.y = acc[i][3];
        *(ulonglong2*)Cp       = v0;
        *(ulonglong2*)(Cp + 4) = v1;
    }
}

// ---------------------------------------------------------------------------
// Scan pass 1: per-chunk carry with zero initial state.
// grid = BATCH*NCH (1024), block = 128 threads; each thread owns 2 states.
// ---------------------------------------------------------------------------
__global__ __launch_bounds__(ST / 2)
void scan1_kernel(const float* __restrict__ A) {
    const int n2 = threadIdx.x;              // state pair index
    const int c = blockIdx.x % NCH;
    const int b = blockIdx.x / NCH;
    const float2 a = ((const float2*)A)[n2];
    const float2* p = (const float2*)(g_uB + ((size_t)(b * LEN + c * CHUNK)) * ST) + n2;
    float2 s = make_float2(0.0f, 0.0f);
    #pragma unroll
    for (int t = 0; t < CHUNK; t++) {
        float2 v = p[(size_t)t * (ST / 2)];
        s.x = fmaf(a.x, s.x, v.x);
        s.y = fmaf(a.y, s.y, v.y);
    }
    ((float2*)g_carry)[(b * NCH + c) * (ST / 2) + n2] = s;
}

// ---------------------------------------------------------------------------
// Scan pass 2: inter-chunk exclusive prefix combine.
// init[c] = state before chunk c; init[0] = x0. grid = BATCH, block = 128.
// ---------------------------------------------------------------------------
__global__ __launch_bounds__(ST / 2)
void scan2_kernel(const float* __restrict__ A, const float* __restrict__ x0) {
    const int n2 = threadIdx.x;
    const int b = blockIdx.x;
    const float2 a = ((const float2*)A)[n2];
    float2 aL = a;
    #pragma unroll
    for (int i = 0; i < 5; i++) { aL.x *= aL.x; aL.y *= aL.y; }   // a^32
    float2 s = ((const float2*)x0)[b * (ST / 2) + n2];
    #pragma unroll
    for (int c = 0; c < NCH; c++) {
        ((float2*)g_init)[(b * NCH + c) * (ST / 2) + n2] = s;
        float2 cv = ((const float2*)g_carry)[(b * NCH + c) * (ST / 2) + n2];
        s.x = fmaf(aL.x, s.x, cv.x);
        s.y = fmaf(aL.y, s.y, cv.y);
    }
}

// ---------------------------------------------------------------------------
// Scan pass 3: full rescan per chunk from true initial state, writes x.
// Last chunk also writes x[:, -1] to the output tail.
// ---------------------------------------------------------------------------
__global__ __launch_bounds__(ST / 2)
void scan3_kernel(const float* __restrict__ A, float* __restrict__ xlast) {
    const int n2 = threadIdx.x;
    const int c = blockIdx.x % NCH;
    const int b = blockIdx.x / NCH;
    const float2 a = ((const float2*)A)[n2];
    float2 s = ((const float2*)g_init)[(b * NCH + c) * (ST / 2) + n2];
    const size_t base = ((size_t)(b * LEN + c * CHUNK)) * (ST / 2) + n2;
    const float2* pin = (const float2*)g_uB;
    float2* pout = (float2*)g_x;
    #pragma unroll
    for (int t = 0; t < CHUNK; t++) {
        float2 v = pin[base + (size_t)t * (ST / 2)];
        s.x = fmaf(a.x, s.x, v.x);
        s.y = fmaf(a.y, s.y, v.y);
        pout[base + (size_t)t * (ST / 2)] = s;
    }
    if (c == NCH - 1) {
        ((float2*)xlast)[b * (ST / 2) + n2] = s;
    }
}

// ---------------------------------------------------------------------------
// kernel_launch
// Inputs (metadata order): u [8,4096,512], x0 [8,256], A [256],
//                          B [512,256], C [256,512]
// Output: y [8,4096,512] flattened, then x_last [8,256].
// ---------------------------------------------------------------------------
extern "C" void kernel_launch(void* const* d_in, const int* in_sizes, int n_in,
                              void* d_out, int out_size) {
    const float* u  = (const float*)d_in[0];
    const float* x0 = (const float*)d_in[1];
    const float* A  = (const float*)d_in[2];
    const float* B  = (const float*)d_in[3];
    const float* C  = (const float*)d_in[4];

    float* y = (float*)d_out;
    float* xlast = y + (size_t)BATCH * LEN * OUTD;

    float* uB_ptr = nullptr;
    float* x_ptr  = nullptr;
    cudaGetSymbolAddress((void**)&uB_ptr, g_uB);
    cudaGetSymbolAddress((void**)&x_ptr,  g_x);

    const int M = BATCH * LEN;   // 32768

    // GEMM1: uB = u @ B   [32768,512] @ [512,256]
    {
        dim3 grid(ST / GBN, M / GBM);
        gemm128<<<grid, 256>>>(u, B, uB_ptr, M, ST, IND);
    }

    // Scan
    scan1_kernel<<<BATCH * NCH, ST / 2>>>(A);
    scan2_kernel<<<BATCH, ST / 2>>>(A, x0);
    scan3_kernel<<<BATCH * NCH, ST / 2>>>(A, xlast);

    // GEMM2: y = x @ C    [32768,256] @ [256,512]
    {
        dim3 grid(OUTD / GBN, M / GBM);
        gemm128<<<grid, 256>>>(x_ptr, C, y, M, OUTD, ST);
    }
}

// round 5
// speedup vs baseline: 1.1677x; 1.1677x over previous
#include <cuda_runtime.h>
#include <cstdint>
#include <cstddef>

// Problem constants
#define BATCH 8
#define LEN   4096
#define IND   512
#define ST    256
#define OUTD  512

#define CHUNK 32
#define NCH   (LEN / CHUNK)   // 128

typedef unsigned long long ull;

// Scratch in device globals (no allocation allowed)
__device__ float g_uB[(size_t)BATCH * LEN * ST];      // 32 MB
__device__ float g_x [(size_t)BATCH * LEN * ST];      // 32 MB
__device__ float g_carry[BATCH * NCH * ST];
__device__ float g_init [BATCH * NCH * ST];

// Packed dual-fp32 FMA (Blackwell FFMA2): d = a*b + d elementwise on f32x2
#define FMA_F32X2(d, a, b) \
    asm("fma.rn.f32x2 %0, %1, %2, %0;" : "+l"(d) : "l"(a), "l"(b))

// ---------------------------------------------------------------------------
// Tiled fp32 GEMM with packed f32x2 FMA, R1 memory layout (proven):
// Cm[M,N] = A[M,K] @ Bm[K,N], row-major. 128x128x16 tile, 256 threads,
// 8x8 microtile, double-buffered smem. Packing to f32x2 done in registers
// (mov.b64), so smem traffic/layout is identical to the 36TF/s scalar kernel
// while the fma-pipe work halves.
// ---------------------------------------------------------------------------
#define GBM 128
#define GBN 128
#define GBK 16

__global__ __launch_bounds__(256)
void gemm128(const float* __restrict__ A, const float* __restrict__ Bm,
             float* __restrict__ Cm, int M, int N, int K) {
    __shared__ float As[2][GBK][GBM];
    __shared__ float Bs[2][GBK][GBN];
    const int tid = threadIdx.x;
    const int rowBase = blockIdx.y * GBM;
    const int colBase = blockIdx.x * GBN;

    // A load: 128 rows x 16 cols; each thread 2 float4 along K (rows r, r+64)
    const int aRow = tid >> 2;           // 0..63
    const int aCol = (tid & 3) * 4;      // 0,4,8,12
    // B load: 16 rows x 128 cols; each thread 2 float4 along N (rows r, r+8)
    const int bRow = tid >> 5;           // 0..7
    const int bCol = (tid & 31) * 4;     // 0..124

    const int tm = (tid >> 4) * 8;       // 0..120
    const int tn = (tid & 15) * 8;       // 0..120

    ull acc[8][4] = {};

    // prologue: tile 0 -> buffer 0
    {
        const float* Ag = A + (size_t)(rowBase + aRow) * K + aCol;
        float4 a0 = *(const float4*)Ag;
        float4 a1 = *(const float4*)(Ag + (size_t)64 * K);
        #pragma unroll
        for (int i = 0; i < 4; i++) {
            As[0][aCol + i][aRow]      = ((const float*)&a0)[i];
            As[0][aCol + i][aRow + 64] = ((const float*)&a1)[i];
        }
        const float* Bg = Bm + (size_t)bRow * N + colBase + bCol;
        *(float4*)&Bs[0][bRow][bCol]     = *(const float4*)Bg;
        *(float4*)&Bs[0][bRow + 8][bCol] = *(const float4*)(Bg + (size_t)8 * N);
    }
    __syncthreads();

    const int nk = K / GBK;
    for (int kt = 0; kt < nk; kt++) {
        const int cur = kt & 1;
        const int nxt = cur ^ 1;
        float4 pa0, pa1, pb0, pb1;
        const bool havenext = (kt + 1 < nk);
        if (havenext) {
            const int k0 = (kt + 1) * GBK;
            const float* Ag = A + (size_t)(rowBase + aRow) * K + k0 + aCol;
            pa0 = *(const float4*)Ag;
            pa1 = *(const float4*)(Ag + (size_t)64 * K);
            const float* Bg = Bm + (size_t)(k0 + bRow) * N + colBase + bCol;
            pb0 = *(const float4*)Bg;
            pb1 = *(const float4*)(Bg + (size_t)8 * N);
        }

        #pragma unroll
        for (int k = 0; k < GBK; k++) {
            float ra[8], rb[8];
            *(float4*)&ra[0] = *(const float4*)&As[cur][k][tm];
            *(float4*)&ra[4] = *(const float4*)&As[cur][k][tm + 4];
            *(float4*)&rb[0] = *(const float4*)&Bs[cur][k][tn];
            *(float4*)&rb[4] = *(const float4*)&Bs[cur][k][tn + 4];

            ull ad[8], bd[4];
            #pragma unroll
            for (int i = 0; i < 8; i++)
                asm("mov.b64 %0, {%1, %1};" : "=l"(ad[i]) : "f"(ra[i]));
            #pragma unroll
            for (int j = 0; j < 4; j++)
                asm("mov.b64 %0, {%1, %2};" : "=l"(bd[j]) : "f"(rb[2*j]), "f"(rb[2*j+1]));

            #pragma unroll
            for (int i = 0; i < 8; i++)
                #pragma unroll
                for (int j = 0; j < 4; j++)
                    FMA_F32X2(acc[i][j], ad[i], bd[j]);
        }

        if (havenext) {
            #pragma unroll
            for (int i = 0; i < 4; i++) {
                As[nxt][aCol + i][aRow]      = ((const float*)&pa0)[i];
                As[nxt][aCol + i][aRow + 64] = ((const float*)&pa1)[i];
            }
            *(float4*)&Bs[nxt][bRow][bCol]     = pb0;
            *(float4*)&Bs[nxt][bRow + 8][bCol] = pb1;
        }
        __syncthreads();
    }

    #pragma unroll
    for (int i = 0; i < 8; i++) {
        float* Cp = &Cm[(size_t)(rowBase + tm + i) * N + colBase + tn];
        ulonglong2 v0; v0.x = acc[i][0]; v0.y = acc[i][1];
        ulonglong2 v1; v1.x = acc[i][2]; v1.y = acc[i][3];
        *(ulonglong2*)Cp       = v0;
        *(ulonglong2*)(Cp + 4) = v1;
    }
}

// ---------------------------------------------------------------------------
// Scan pass 1: per-chunk carry with zero initial state.
// grid = BATCH*NCH (1024), block = 128 threads; each thread owns 2 states.
// ---------------------------------------------------------------------------
__global__ __launch_bounds__(ST / 2)
void scan1_kernel(const float* __restrict__ A) {
    const int n2 = threadIdx.x;              // state pair index
    const int c = blockIdx.x % NCH;
    const int b = blockIdx.x / NCH;
    const float2 a = ((const float2*)A)[n2];
    const float2* p = (const float2*)(g_uB + ((size_t)(b * LEN + c * CHUNK)) * ST) + n2;
    float2 s = make_float2(0.0f, 0.0f);
    #pragma unroll
    for (int t = 0; t < CHUNK; t++) {
        float2 v = p[(size_t)t * (ST / 2)];
        s.x = fmaf(a.x, s.x, v.x);
        s.y = fmaf(a.y, s.y, v.y);
    }
    ((float2*)g_carry)[(b * NCH + c) * (ST / 2) + n2] = s;
}

// ---------------------------------------------------------------------------
// Scan pass 2: inter-chunk exclusive prefix combine.
// ---------------------------------------------------------------------------
__global__ __launch_bounds__(ST / 2)
void scan2_kernel(const float* __restrict__ A, const float* __restrict__ x0) {
    const int n2 = threadIdx.x;
    const int b = blockIdx.x;
    const float2 a = ((const float2*)A)[n2];
    float2 aL = a;
    #pragma unroll
    for (int i = 0; i < 5; i++) { aL.x *= aL.x; aL.y *= aL.y; }   // a^32
    float2 s = ((const float2*)x0)[b * (ST / 2) + n2];
    #pragma unroll
    for (int c = 0; c < NCH; c++) {
        ((float2*)g_init)[(b * NCH + c) * (ST / 2) + n2] = s;
        float2 cv = ((const float2*)g_carry)[(b * NCH + c) * (ST / 2) + n2];
        s.x = fmaf(aL.x, s.x, cv.x);
        s.y = fmaf(aL.y, s.y, cv.y);
    }
}

// ---------------------------------------------------------------------------
// Scan pass 3: full rescan per chunk from true initial state, writes x.
// ---------------------------------------------------------------------------
__global__ __launch_bounds__(ST / 2)
void scan3_kernel(const float* __restrict__ A, float* __restrict__ xlast) {
    const int n2 = threadIdx.x;
    const int c = blockIdx.x % NCH;
    const int b = blockIdx.x / NCH;
    const float2 a = ((const float2*)A)[n2];
    float2 s = ((const float2*)g_init)[(b * NCH + c) * (ST / 2) + n2];
    const size_t base = ((size_t)(b * LEN + c * CHUNK)) * (ST / 2) + n2;
    const float2* pin = (const float2*)g_uB;
    float2* pout = (float2*)g_x;
    #pragma unroll
    for (int t = 0; t < CHUNK; t++) {
        float2 v = pin[base + (size_t)t * (ST / 2)];
        s.x = fmaf(a.x, s.x, v.x);
        s.y = fmaf(a.y, s.y, v.y);
        pout[base + (size_t)t * (ST / 2)] = s;
    }
    if (c == NCH - 1) {
        ((float2*)xlast)[b * (ST / 2) + n2] = s;
    }
}

// ---------------------------------------------------------------------------
// kernel_launch
// Inputs: u [8,4096,512], x0 [8,256], A [256], B [512,256], C [256,512]
// Output: y [8,4096,512] flattened, then x_last [8,256].
// ---------------------------------------------------------------------------
extern "C" void kernel_launch(void* const* d_in, const int* in_sizes, int n_in,
                              void* d_out, int out_size) {
    const float* u  = (const float*)d_in[0];
    const float* x0 = (const float*)d_in[1];
    const float* A  = (const float*)d_in[2];
    const float* B  = (const float*)d_in[3];
    const float* C  = (const float*)d_in[4];

    float* y = (float*)d_out;
    float* xlast = y + (size_t)BATCH * LEN * OUTD;

    float *uB_ptr, *x_ptr;
    cudaGetSymbolAddress((void**)&uB_ptr, g_uB);
    cudaGetSymbolAddress((void**)&x_ptr,  g_x);

    const int M = BATCH * LEN;   // 32768

    // GEMM1: uB = u @ B   [32768,512] @ [512,256]
    {
        dim3 grid(ST / GBN, M / GBM);
        gemm128<<<grid, 256>>>(u, B, uB_ptr, M, ST, IND);
    }

    // Scan
    scan1_kernel<<<BATCH * NCH, ST / 2>>>(A);
    scan2_kernel<<<BATCH, ST / 2>>>(A, x0);
    scan3_kernel<<<BATCH * NCH, ST / 2>>>(A, xlast);

    // GEMM2: y = x @ C    [32768,256] @ [256,512]
    {
        dim3 grid(OUTD / GBN, M / GBM);
        gemm128<<<grid, 256>>>(x_ptr, C, y, M, OUTD, ST);
    }
}

// round 6
// speedup vs baseline: 2.4007x; 2.0558x over previous
#include <cuda_runtime.h>
#include <cuda_fp16.h>
#include <cstdint>
#include <cstddef>

// Problem constants
#define BATCH 8
#define LEN   4096
#define IND   512
#define ST    256
#define OUTD  512

#define CHUNK 32
#define NCH   (LEN / CHUNK)   // 128

// Scratch in device globals (no allocation allowed)
__device__ float g_uB[(size_t)BATCH * LEN * ST];      // 32 MB
__device__ float g_x [(size_t)BATCH * LEN * ST];      // 32 MB
__device__ float g_carry[BATCH * NCH * ST];
__device__ float g_init [BATCH * NCH * ST];

// ---------------------------------------------------------------------------
// HMMA fp16-split GEMM:  Cm[M,N] = Am[M,K] @ Bm[K,N]  (row-major, fp32 I/O)
// fp32 = hi(fp16) + lo(fp16); 3 mma passes (hh, hl, lh) give ~2^-22 accuracy.
// Tile 128x128x32, 8 warps, warp tile 32x64 (2 x m16, 8 x n8), fp32 accum.
// ---------------------------------------------------------------------------
#define BM 128
#define BN 128
#define BKK 32
#define ALD 40    // A smem leading dim in halves (pad 32->40: conflict-free ldmatrix)
#define BLD 136   // B smem leading dim in halves (pad 128->136)
#define A_SZ (BM * ALD)                 // 5120 halves
#define B_SZ (BKK * BLD)                // 4352 halves
#define STAGE_H (2 * A_SZ + 2 * B_SZ)   // 18944 halves
#define GEMM_SMEM (2 * STAGE_H * 2)     // 75776 bytes

__device__ __forceinline__ uint32_t smem_u32(const void* p) {
    uint32_t a;
    asm("{ .reg .u64 t; cvta.to.shared.u64 t, %1; cvt.u32.u64 %0, t; }"
        : "=r"(a) : "l"(p));
    return a;
}

#define LDSM_X4(r, addr) \
    asm volatile("ldmatrix.sync.aligned.m8n8.x4.shared.b16 {%0,%1,%2,%3}, [%4];" \
        : "=r"((r)[0]), "=r"((r)[1]), "=r"((r)[2]), "=r"((r)[3]) : "r"(addr))

#define LDSM_X4T(r, addr) \
    asm volatile("ldmatrix.sync.aligned.m8n8.x4.trans.shared.b16 {%0,%1,%2,%3}, [%4];" \
        : "=r"((r)[0]), "=r"((r)[1]), "=r"((r)[2]), "=r"((r)[3]) : "r"(addr))

#define MMA16816(d, a, b0, b1) \
    asm volatile("mma.sync.aligned.m16n8k16.row.col.f32.f16.f16.f32 " \
        "{%0,%1,%2,%3}, {%4,%5,%6,%7}, {%8,%9}, {%0,%1,%2,%3};" \
        : "+f"((d)[0]), "+f"((d)[1]), "+f"((d)[2]), "+f"((d)[3]) \
        : "r"((a)[0]), "r"((a)[1]), "r"((a)[2]), "r"((a)[3]), \
          "r"(b0), "r"(b1))

// Convert 16 fp32 -> 16 hi-halves + 16 lo-halves, store as 2x16B each.
__device__ __forceinline__ void cvt_store16(half* hi, half* lo, const float* v) {
    half2 h[8], l[8];
    #pragma unroll
    for (int i = 0; i < 8; i++) {
        float f0 = v[2 * i], f1 = v[2 * i + 1];
        half h0 = __float2half_rn(f0), h1 = __float2half_rn(f1);
        h[i] = __halves2half2(h0, h1);
        l[i] = __halves2half2(__float2half_rn(f0 - __half2float(h0)),
                              __float2half_rn(f1 - __half2float(h1)));
    }
    *(uint4*)hi       = *(uint4*)&h[0];
    *(uint4*)(hi + 8) = *(uint4*)&h[4];
    *(uint4*)lo       = *(uint4*)&l[0];
    *(uint4*)(lo + 8) = *(uint4*)&l[4];
}

__global__ __launch_bounds__(256)
void gemm_hmma(const float* __restrict__ Am, const float* __restrict__ Bm,
               float* __restrict__ Cm, int M, int N, int K) {
    extern __shared__ half sm[];
    const int tid = threadIdx.x;
    const int lane = tid & 31, wid = tid >> 5;
    const int warp_m = wid & 3;   // 4 warps over M (32 rows each)
    const int warp_n = wid >> 2;  // 2 warps over N (64 cols each)
    const int rowBase = blockIdx.y * BM;
    const int colBase = blockIdx.x * BN;

    // Loader mapping
    const int ar = tid >> 1, ac = (tid & 1) * 16;   // A: 128 rows x 32 cols
    const int br = tid >> 3, bc = (tid & 7) * 16;   // B: 32 rows x 128 cols

    const float* Ag = Am + (size_t)(rowBase + ar) * K + ac;
    const float* Bg = Bm + (size_t)br * N + colBase + bc;

    float acc[2][8][4] = {};

    // prologue: load + convert + store stage 0
    {
        float pa[16], pb[16];
        #pragma unroll
        for (int i = 0; i < 4; i++) *(float4*)&pa[i * 4] = *(const float4*)(Ag + i * 4);
        #pragma unroll
        for (int i = 0; i < 4; i++) *(float4*)&pb[i * 4] = *(const float4*)(Bg + i * 4);
        half* Ah = sm;
        half* Al = Ah + A_SZ;
        half* Bh = Al + A_SZ;
        half* Bl = Bh + B_SZ;
        cvt_store16(Ah + ar * ALD + ac, Al + ar * ALD + ac, pa);
        cvt_store16(Bh + br * BLD + bc, Bl + br * BLD + bc, pb);
    }
    __syncthreads();

    const int nst = K / BKK;
    for (int s = 0; s < nst; s++) {
        const int cur = s & 1;
        const bool more = (s + 1 < nst);
        float pa[16], pb[16];
        if (more) {
            const float* Ag2 = Ag + (s + 1) * BKK;
            const float* Bg2 = Bg + (size_t)(s + 1) * BKK * N;
            #pragma unroll
            for (int i = 0; i < 4; i++) *(float4*)&pa[i * 4] = *(const float4*)(Ag2 + i * 4);
            #pragma unroll
            for (int i = 0; i < 4; i++) *(float4*)&pb[i * 4] = *(const float4*)(Bg2 + i * 4);
        }

        // compute on stage cur
        {
            half* Ah = sm + (size_t)cur * STAGE_H;
            half* Al = Ah + A_SZ;
            half* Bh = Al + A_SZ;
            half* Bl = Bh + B_SZ;
            #pragma unroll
            for (int k16 = 0; k16 < 2; k16++) {
                uint32_t ah[2][4], al[2][4], bh[4][4], bl[4][4];
                const int arow = warp_m * 32 + (lane & 15);
                const int acol = k16 * 16 + (lane >> 4) * 8;
                #pragma unroll
                for (int mi = 0; mi < 2; mi++) {
                    LDSM_X4(ah[mi], smem_u32(&Ah[(arow + mi * 16) * ALD + acol]));
                    LDSM_X4(al[mi], smem_u32(&Al[(arow + mi * 16) * ALD + acol]));
                }
                const int brow = k16 * 16 + (lane & 15);
                const int bcol = warp_n * 64 + (lane >> 4) * 8;
                #pragma unroll
                for (int ni = 0; ni < 4; ni++) {
                    LDSM_X4T(bh[ni], smem_u32(&Bh[brow * BLD + bcol + ni * 16]));
                    LDSM_X4T(bl[ni], smem_u32(&Bl[brow * BLD + bcol + ni * 16]));
                }
                #pragma unroll
                for (int mi = 0; mi < 2; mi++)
                    #pragma unroll
                    for (int nj = 0; nj < 8; nj++) {
                        const int ni = nj >> 1, ro = (nj & 1) * 2;
                        MMA16816(acc[mi][nj], ah[mi], bh[ni][ro], bh[ni][ro + 1]);
                        MMA16816(acc[mi][nj], ah[mi], bl[ni][ro], bl[ni][ro + 1]);
                        MMA16816(acc[mi][nj], al[mi], bh[ni][ro], bh[ni][ro + 1]);
                    }
            }
        }

        if (more) {
            half* Ah = sm + (size_t)(cur ^ 1) * STAGE_H;
            half* Al = Ah + A_SZ;
            half* Bh = Al + A_SZ;
            half* Bl = Bh + B_SZ;
            cvt_store16(Ah + ar * ALD + ac, Al + ar * ALD + ac, pa);
            cvt_store16(Bh + br * BLD + bc, Bl + br * BLD + bc, pb);
        }
        __syncthreads();
    }

    // Epilogue: mma fragment layout -> gmem fp32
    const int g = lane >> 2;
    const int cc = (lane & 3) * 2;
    #pragma unroll
    for (int mi = 0; mi < 2; mi++) {
        const int r0 = rowBase + warp_m * 32 + mi * 16 + g;
        #pragma unroll
        for (int nj = 0; nj < 8; nj++) {
            const int c0 = colBase + warp_n * 64 + nj * 8 + cc;
            *(float2*)&Cm[(size_t)r0 * N + c0]       = make_float2(acc[mi][nj][0], acc[mi][nj][1]);
            *(float2*)&Cm[(size_t)(r0 + 8) * N + c0] = make_float2(acc[mi][nj][2], acc[mi][nj][3]);
        }
    }
}

// ---------------------------------------------------------------------------
// Scan pass 1: per-chunk carry with zero initial state.
// ---------------------------------------------------------------------------
__global__ __launch_bounds__(ST / 2)
void scan1_kernel(const float* __restrict__ A) {
    const int n2 = threadIdx.x;
    const int c = blockIdx.x % NCH;
    const int b = blockIdx.x / NCH;
    const float2 a = ((const float2*)A)[n2];
    const float2* p = (const float2*)(g_uB + ((size_t)(b * LEN + c * CHUNK)) * ST) + n2;
    float2 s = make_float2(0.0f, 0.0f);
    #pragma unroll
    for (int t = 0; t < CHUNK; t++) {
        float2 v = p[(size_t)t * (ST / 2)];
        s.x = fmaf(a.x, s.x, v.x);
        s.y = fmaf(a.y, s.y, v.y);
    }
    ((float2*)g_carry)[(b * NCH + c) * (ST / 2) + n2] = s;
}

// ---------------------------------------------------------------------------
// Scan pass 2: inter-chunk exclusive prefix combine.
// ---------------------------------------------------------------------------
__global__ __launch_bounds__(ST / 2)
void scan2_kernel(const float* __restrict__ A, const float* __restrict__ x0) {
    const int n2 = threadIdx.x;
    const int b = blockIdx.x;
    const float2 a = ((const float2*)A)[n2];
    float2 aL = a;
    #pragma unroll
    for (int i = 0; i < 5; i++) { aL.x *= aL.x; aL.y *= aL.y; }   // a^32
    float2 s = ((const float2*)x0)[b * (ST / 2) + n2];
    #pragma unroll
    for (int c = 0; c < NCH; c++) {
        ((float2*)g_init)[(b * NCH + c) * (ST / 2) + n2] = s;
        float2 cv = ((const float2*)g_carry)[(b * NCH + c) * (ST / 2) + n2];
        s.x = fmaf(aL.x, s.x, cv.x);
        s.y = fmaf(aL.y, s.y, cv.y);
    }
}

// ---------------------------------------------------------------------------
// Scan pass 3: full rescan per chunk from true initial state, writes x.
// ---------------------------------------------------------------------------
__global__ __launch_bounds__(ST / 2)
void scan3_kernel(const float* __restrict__ A, float* __restrict__ xlast) {
    const int n2 = threadIdx.x;
    const int c = blockIdx.x % NCH;
    const int b = blockIdx.x / NCH;
    const float2 a = ((const float2*)A)[n2];
    float2 s = ((const float2*)g_init)[(b * NCH + c) * (ST / 2) + n2];
    const size_t base = ((size_t)(b * LEN + c * CHUNK)) * (ST / 2) + n2;
    const float2* pin = (const float2*)g_uB;
    float2* pout = (float2*)g_x;
    #pragma unroll
    for (int t = 0; t < CHUNK; t++) {
        float2 v = pin[base + (size_t)t * (ST / 2)];
        s.x = fmaf(a.x, s.x, v.x);
        s.y = fmaf(a.y, s.y, v.y);
        pout[base + (size_t)t * (ST / 2)] = s;
    }
    if (c == NCH - 1) {
        ((float2*)xlast)[b * (ST / 2) + n2] = s;
    }
}

// ---------------------------------------------------------------------------
// kernel_launch
// Inputs: u [8,4096,512], x0 [8,256], A [256], B [512,256], C [256,512]
// Output: y [8,4096,512] flattened, then x_last [8,256].
// ---------------------------------------------------------------------------
extern "C" void kernel_launch(void* const* d_in, const int* in_sizes, int n_in,
                              void* d_out, int out_size) {
    const float* u  = (const float*)d_in[0];
    const float* x0 = (const float*)d_in[1];
    const float* A  = (const float*)d_in[2];
    const float* B  = (const float*)d_in[3];
    const float* C  = (const float*)d_in[4];

    float* y = (float*)d_out;
    float* xlast = y + (size_t)BATCH * LEN * OUTD;

    float *uB_ptr, *x_ptr;
    cudaGetSymbolAddress((void**)&uB_ptr, g_uB);
    cudaGetSymbolAddress((void**)&x_ptr,  g_x);

    cudaFuncSetAttribute(gemm_hmma, cudaFuncAttributeMaxDynamicSharedMemorySize, GEMM_SMEM);

    const int M = BATCH * LEN;   // 32768

    // GEMM1: uB = u @ B   [32768,512] @ [512,256]
    {
        dim3 grid(ST / BN, M / BM);
        gemm_hmma<<<grid, 256, GEMM_SMEM>>>(u, B, uB_ptr, M, ST, IND);
    }

    // Scan
    scan1_kernel<<<BATCH * NCH, ST / 2>>>(A);
    scan2_kernel<<<BATCH, ST / 2>>>(A, x0);
    scan3_kernel<<<BATCH * NCH, ST / 2>>>(A, xlast);

    // GEMM2: y = x @ C    [32768,256] @ [256,512]
    {
        dim3 grid(OUTD / BN, M / BM);
        gemm_hmma<<<grid, 256, GEMM_SMEM>>>(x_ptr, C, y, M, OUTD, ST);
    }
}

// round 7
// speedup vs baseline: 2.6383x; 1.0990x over previous
#include <cuda_runtime.h>
#include <cuda_fp16.h>
#include <cstdint>
#include <cstddef>

// Problem constants
#define BATCH 8
#define LEN   4096
#define IND   512
#define ST    256
#define OUTD  512

#define CHUNK 32
#define NCH   (LEN / CHUNK)   // 128

// Scratch in device globals (no allocation allowed)
__device__ float g_uB[(size_t)BATCH * LEN * ST];      // 32 MB
__device__ float g_x [(size_t)BATCH * LEN * ST];      // 32 MB
__device__ float g_carry[BATCH * NCH * ST];
__device__ float g_init [BATCH * NCH * ST];

// ---------------------------------------------------------------------------
// HMMA asymmetric-split GEMM:  Cm[M,N] = Am[M,K] @ Bm[K,N]  (row-major fp32)
// A rounded to fp16 once (Ah); B split fp32 = Bh + Bl. Two mma passes:
//   acc += Ah*Bh + Ah*Bl  ==  Ah * B (exact in B)
// Dropped term (A-Ah)*B ~ 2^-13 relative. Tile 128x128x32, 8 warps,
// warp tile 32x64, fp32 accumulate.
// ---------------------------------------------------------------------------
#define BM 128
#define BN 128
#define BKK 32
#define ALD 40    // A smem leading dim in halves (pad 32->40)
#define BLD 136   // B smem leading dim in halves (pad 128->136)
#define A_SZ (BM * ALD)                 // 5120 halves
#define B_SZ (BKK * BLD)                // 4352 halves
#define STAGE_H (A_SZ + 2 * B_SZ)       // 13824 halves
#define GEMM_SMEM (2 * STAGE_H * 2)     // 55296 bytes

__device__ __forceinline__ uint32_t smem_u32(const void* p) {
    uint32_t a;
    asm("{ .reg .u64 t; cvta.to.shared.u64 t, %1; cvt.u32.u64 %0, t; }"
        : "=r"(a) : "l"(p));
    return a;
}

#define LDSM_X4(r, addr) \
    asm volatile("ldmatrix.sync.aligned.m8n8.x4.shared.b16 {%0,%1,%2,%3}, [%4];" \
        : "=r"((r)[0]), "=r"((r)[1]), "=r"((r)[2]), "=r"((r)[3]) : "r"(addr))

#define LDSM_X4T(r, addr) \
    asm volatile("ldmatrix.sync.aligned.m8n8.x4.trans.shared.b16 {%0,%1,%2,%3}, [%4];" \
        : "=r"((r)[0]), "=r"((r)[1]), "=r"((r)[2]), "=r"((r)[3]) : "r"(addr))

#define MMA16816(d, a, b0, b1) \
    asm volatile("mma.sync.aligned.m16n8k16.row.col.f32.f16.f16.f32 " \
        "{%0,%1,%2,%3}, {%4,%5,%6,%7}, {%8,%9}, {%0,%1,%2,%3};" \
        : "+f"((d)[0]), "+f"((d)[1]), "+f"((d)[2]), "+f"((d)[3]) \
        : "r"((a)[0]), "r"((a)[1]), "r"((a)[2]), "r"((a)[3]), \
          "r"(b0), "r"(b1))

// Convert 16 fp32 -> 16 fp16 (round-to-nearest), store 32 bytes.
__device__ __forceinline__ void cvt_storeA(half* hi, const float* v) {
    half2 h[8];
    #pragma unroll
    for (int i = 0; i < 8; i++)
        h[i] = __halves2half2(__float2half_rn(v[2 * i]), __float2half_rn(v[2 * i + 1]));
    *(uint4*)hi       = *(uint4*)&h[0];
    *(uint4*)(hi + 8) = *(uint4*)&h[4];
}

// Convert 16 fp32 -> hi + lo fp16 splits, store 32 bytes each.
__device__ __forceinline__ void cvt_storeHL(half* hi, half* lo, const float* v) {
    half2 h[8], l[8];
    #pragma unroll
    for (int i = 0; i < 8; i++) {
        float f0 = v[2 * i], f1 = v[2 * i + 1];
        half h0 = __float2half_rn(f0), h1 = __float2half_rn(f1);
        h[i] = __halves2half2(h0, h1);
        l[i] = __halves2half2(__float2half_rn(f0 - __half2float(h0)),
                              __float2half_rn(f1 - __half2float(h1)));
    }
    *(uint4*)hi       = *(uint4*)&h[0];
    *(uint4*)(hi + 8) = *(uint4*)&h[4];
    *(uint4*)lo       = *(uint4*)&l[0];
    *(uint4*)(lo + 8) = *(uint4*)&l[4];
}

__global__ __launch_bounds__(256)
void gemm_hmma(const float* __restrict__ Am, const float* __restrict__ Bm,
               float* __restrict__ Cm, int M, int N, int K) {
    extern __shared__ half sm[];
    const int tid = threadIdx.x;
    const int lane = tid & 31, wid = tid >> 5;
    const int warp_m = wid & 3;   // 4 warps over M (32 rows each)
    const int warp_n = wid >> 2;  // 2 warps over N (64 cols each)
    const int rowBase = blockIdx.y * BM;
    const int colBase = blockIdx.x * BN;

    // Loader mapping
    const int ar = tid >> 1, ac = (tid & 1) * 16;   // A: 128 rows x 32 cols
    const int br = tid >> 3, bc = (tid & 7) * 16;   // B: 32 rows x 128 cols

    const float* Ag = Am + (size_t)(rowBase + ar) * K + ac;
    const float* Bg = Bm + (size_t)br * N + colBase + bc;

    float acc[2][8][4] = {};

    // prologue: load + convert + store stage 0
    {
        float pa[16], pb[16];
        #pragma unroll
        for (int i = 0; i < 4; i++) *(float4*)&pa[i * 4] = *(const float4*)(Ag + i * 4);
        #pragma unroll
        for (int i = 0; i < 4; i++) *(float4*)&pb[i * 4] = *(const float4*)(Bg + i * 4);
        half* Ah = sm;
        half* Bh = Ah + A_SZ;
        half* Bl = Bh + B_SZ;
        cvt_storeA(Ah + ar * ALD + ac, pa);
        cvt_storeHL(Bh + br * BLD + bc, Bl + br * BLD + bc, pb);
    }
    __syncthreads();

    const int nst = K / BKK;
    for (int s = 0; s < nst; s++) {
        const int cur = s & 1;
        const bool more = (s + 1 < nst);
        float pa[16], pb[16];
        if (more) {
            const float* Ag2 = Ag + (s + 1) * BKK;
            const float* Bg2 = Bg + (size_t)(s + 1) * BKK * N;
            #pragma unroll
            for (int i = 0; i < 4; i++) *(float4*)&pa[i * 4] = *(const float4*)(Ag2 + i * 4);
            #pragma unroll
            for (int i = 0; i < 4; i++) *(float4*)&pb[i * 4] = *(const float4*)(Bg2 + i * 4);
        }

        // compute on stage cur
        {
            half* Ah = sm + (size_t)cur * STAGE_H;
            half* Bh = Ah + A_SZ;
            half* Bl = Bh + B_SZ;
            #pragma unroll
            for (int k16 = 0; k16 < 2; k16++) {
                uint32_t ah[2][4], bh[4][4], bl[4][4];
                const int arow = warp_m * 32 + (lane & 15);
                const int acol = k16 * 16 + (lane >> 4) * 8;
                #pragma unroll
                for (int mi = 0; mi < 2; mi++)
                    LDSM_X4(ah[mi], smem_u32(&Ah[(arow + mi * 16) * ALD + acol]));
                const int brow = k16 * 16 + (lane & 15);
                const int bcol = warp_n * 64 + (lane >> 4) * 8;
                #pragma unroll
                for (int ni = 0; ni < 4; ni++) {
                    LDSM_X4T(bh[ni], smem_u32(&Bh[brow * BLD + bcol + ni * 16]));
                    LDSM_X4T(bl[ni], smem_u32(&Bl[brow * BLD + bcol + ni * 16]));
                }
                #pragma unroll
                for (int mi = 0; mi < 2; mi++)
                    #pragma unroll
                    for (int nj = 0; nj < 8; nj++) {
                        const int ni = nj >> 1, ro = (nj & 1) * 2;
                        MMA16816(acc[mi][nj], ah[mi], bh[ni][ro], bh[ni][ro + 1]);
                        MMA16816(acc[mi][nj], ah[mi], bl[ni][ro], bl[ni][ro + 1]);
                    }
            }
        }

        if (more) {
            half* Ah = sm + (size_t)(cur ^ 1) * STAGE_H;
            half* Bh = Ah + A_SZ;
            half* Bl = Bh + B_SZ;
            cvt_storeA(Ah + ar * ALD + ac, pa);
            cvt_storeHL(Bh + br * BLD + bc, Bl + br * BLD + bc, pb);
        }
        __syncthreads();
    }

    // Epilogue: mma fragment layout -> gmem fp32
    const int g = lane >> 2;
    const int cc = (lane & 3) * 2;
    #pragma unroll
    for (int mi = 0; mi < 2; mi++) {
        const int r0 = rowBase + warp_m * 32 + mi * 16 + g;
        #pragma unroll
        for (int nj = 0; nj < 8; nj++) {
            const int c0 = colBase + warp_n * 64 + nj * 8 + cc;
            *(float2*)&Cm[(size_t)r0 * N + c0]       = make_float2(acc[mi][nj][0], acc[mi][nj][1]);
            *(float2*)&Cm[(size_t)(r0 + 8) * N + c0] = make_float2(acc[mi][nj][2], acc[mi][nj][3]);
        }
    }
}

// ---------------------------------------------------------------------------
// Scan pass 1: per-chunk carry with zero initial state.
// ---------------------------------------------------------------------------
__global__ __launch_bounds__(ST / 2)
void scan1_kernel(const float* __restrict__ A) {
    const int n2 = threadIdx.x;
    const int c = blockIdx.x % NCH;
    const int b = blockIdx.x / NCH;
    const float2 a = ((const float2*)A)[n2];
    const float2* p = (const float2*)(g_uB + ((size_t)(b * LEN + c * CHUNK)) * ST) + n2;
    float2 s = make_float2(0.0f, 0.0f);
    #pragma unroll
    for (int t = 0; t < CHUNK; t++) {
        float2 v = p[(size_t)t * (ST / 2)];
        s.x = fmaf(a.x, s.x, v.x);
        s.y = fmaf(a.y, s.y, v.y);
    }
    ((float2*)g_carry)[(b * NCH + c) * (ST / 2) + n2] = s;
}

// ---------------------------------------------------------------------------
// Scan pass 2: inter-chunk exclusive prefix combine.
// ---------------------------------------------------------------------------
__global__ __launch_bounds__(ST / 2)
void scan2_kernel(const float* __restrict__ A, const float* __restrict__ x0) {
    const int n2 = threadIdx.x;
    const int b = blockIdx.x;
    const float2 a = ((const float2*)A)[n2];
    float2 aL = a;
    #pragma unroll
    for (int i = 0; i < 5; i++) { aL.x *= aL.x; aL.y *= aL.y; }   // a^32
    float2 s = ((const float2*)x0)[b * (ST / 2) + n2];
    #pragma unroll
    for (int c = 0; c < NCH; c++) {
        ((float2*)g_init)[(b * NCH + c) * (ST / 2) + n2] = s;
        float2 cv = ((const float2*)g_carry)[(b * NCH + c) * (ST / 2) + n2];
        s.x = fmaf(aL.x, s.x, cv.x);
        s.y = fmaf(aL.y, s.y, cv.y);
    }
}

// ---------------------------------------------------------------------------
// Scan pass 3: full rescan per chunk from true initial state, writes x.
// ---------------------------------------------------------------------------
__global__ __launch_bounds__(ST / 2)
void scan3_kernel(const float* __restrict__ A, float* __restrict__ xlast) {
    const int n2 = threadIdx.x;
    const int c = blockIdx.x % NCH;
    const int b = blockIdx.x / NCH;
    const float2 a = ((const float2*)A)[n2];
    float2 s = ((const float2*)g_init)[(b * NCH + c) * (ST / 2) + n2];
    const size_t base = ((size_t)(b * LEN + c * CHUNK)) * (ST / 2) + n2;
    const float2* pin = (const float2*)g_uB;
    float2* pout = (float2*)g_x;
    #pragma unroll
    for (int t = 0; t < CHUNK; t++) {
        float2 v = pin[base + (size_t)t * (ST / 2)];
        s.x = fmaf(a.x, s.x, v.x);
        s.y = fmaf(a.y, s.y, v.y);
        pout[base + (size_t)t * (ST / 2)] = s;
    }
    if (c == NCH - 1) {
        ((float2*)xlast)[b * (ST / 2) + n2] = s;
    }
}

// ---------------------------------------------------------------------------
// kernel_launch
// Inputs: u [8,4096,512], x0 [8,256], A [256], B [512,256], C [256,512]
// Output: y [8,4096,512] flattened, then x_last [8,256].
// ---------------------------------------------------------------------------
extern "C" void kernel_launch(void* const* d_in, const int* in_sizes, int n_in,
                              void* d_out, int out_size) {
    const float* u  = (const float*)d_in[0];
    const float* x0 = (const float*)d_in[1];
    const float* A  = (const float*)d_in[2];
    const float* B  = (const float*)d_in[3];
    const float* C  = (const float*)d_in[4];

    float* y = (float*)d_out;
    float* xlast = y + (size_t)BATCH * LEN * OUTD;

    float *uB_ptr, *x_ptr;
    cudaGetSymbolAddress((void**)&uB_ptr, g_uB);
    cudaGetSymbolAddress((void**)&x_ptr,  g_x);

    cudaFuncSetAttribute(gemm_hmma, cudaFuncAttributeMaxDynamicSharedMemorySize, GEMM_SMEM);

    const int M = BATCH * LEN;   // 32768

    // GEMM1: uB = u @ B   [32768,512] @ [512,256]
    {
        dim3 grid(ST / BN, M / BM);
        gemm_hmma<<<grid, 256, GEMM_SMEM>>>(u, B, uB_ptr, M, ST, IND);
    }

    // Scan
    scan1_kernel<<<BATCH * NCH, ST / 2>>>(A);
    scan2_kernel<<<BATCH, ST / 2>>>(A, x0);
    scan3_kernel<<<BATCH * NCH, ST / 2>>>(A, xlast);

    // GEMM2: y = x @ C    [32768,256] @ [256,512]
    {
        dim3 grid(OUTD / BN, M / BM);
        gemm_hmma<<<grid, 256, GEMM_SMEM>>>(x_ptr, C, y, M, OUTD, ST);
    }
}

// round 8
// speedup vs baseline: 3.1729x; 1.2026x over previous
#include <cuda_runtime.h>
#include <cuda_fp16.h>
#include <cstdint>
#include <cstddef>

// Problem constants
#define BATCH 8
#define LEN   4096
#define IND   512
#define ST    256
#define OUTD  512

#define CHUNK 32
#define NCH   (LEN / CHUNK)   // 128

// Scratch in device globals (no allocation allowed)
__device__ float g_uB[(size_t)BATCH * LEN * ST];      // 32 MB (fp32 scan input)
__device__ half  g_uh[(size_t)BATCH * LEN * IND];     // 32 MB (u as fp16)
__device__ half  g_xh[(size_t)BATCH * LEN * ST];      // 16 MB (x as fp16)
__device__ float g_carry[BATCH * NCH * ST];
__device__ float g_init [BATCH * NCH * ST];
__device__ half  g_Bh[IND * ST], g_Bl[IND * ST];      // B split
__device__ half  g_Ch[ST * OUTD], g_Cl[ST * OUTD];    // C split

// ---------------------------------------------------------------------------
// HMMA asymmetric-split GEMM, all-half inputs (pre-converted):
//   Cm[M,N](fp32) = Ah[M,K](fp16) @ (Bh + Bl)[K,N](fp16 split of fp32 weight)
// Tile 128x128x32, 8 warps, warp tile 32x64, fp32 accumulate, 2 mma passes.
// ---------------------------------------------------------------------------
#define BM 128
#define BN 128
#define BKK 32
#define ALD 40    // A smem leading dim in halves (pad 32->40)
#define BLD 136   // B smem leading dim in halves (pad 128->136)
#define A_SZ (BM * ALD)                 // 5120 halves
#define B_SZ (BKK * BLD)                // 4352 halves
#define STAGE_H (A_SZ + 2 * B_SZ)       // 13824 halves
#define GEMM_SMEM (2 * STAGE_H * 2)     // 55296 bytes

__device__ __forceinline__ uint32_t smem_u32(const void* p) {
    uint32_t a;
    asm("{ .reg .u64 t; cvta.to.shared.u64 t, %1; cvt.u32.u64 %0, t; }"
        : "=r"(a) : "l"(p));
    return a;
}

#define LDSM_X4(r, addr) \
    asm volatile("ldmatrix.sync.aligned.m8n8.x4.shared.b16 {%0,%1,%2,%3}, [%4];" \
        : "=r"((r)[0]), "=r"((r)[1]), "=r"((r)[2]), "=r"((r)[3]) : "r"(addr))

#define LDSM_X4T(r, addr) \
    asm volatile("ldmatrix.sync.aligned.m8n8.x4.trans.shared.b16 {%0,%1,%2,%3}, [%4];" \
        : "=r"((r)[0]), "=r"((r)[1]), "=r"((r)[2]), "=r"((r)[3]) : "r"(addr))

#define MMA16816(d, a, b0, b1) \
    asm volatile("mma.sync.aligned.m16n8k16.row.col.f32.f16.f16.f32 " \
        "{%0,%1,%2,%3}, {%4,%5,%6,%7}, {%8,%9}, {%0,%1,%2,%3};" \
        : "+f"((d)[0]), "+f"((d)[1]), "+f"((d)[2]), "+f"((d)[3]) \
        : "r"((a)[0]), "r"((a)[1]), "r"((a)[2]), "r"((a)[3]), \
          "r"(b0), "r"(b1))

__global__ __launch_bounds__(256)
void gemm_hmma_h(const half* __restrict__ Ag_, const half* __restrict__ Bhg,
                 const half* __restrict__ Blg, float* __restrict__ Cm,
                 int M, int N, int K) {
    extern __shared__ half sm[];
    const int tid = threadIdx.x;
    const int lane = tid & 31, wid = tid >> 5;
    const int warp_m = wid & 3;   // 4 warps over M (32 rows each)
    const int warp_n = wid >> 2;  // 2 warps over N (64 cols each)
    const int rowBase = blockIdx.y * BM;
    const int colBase = blockIdx.x * BN;

    // Loader mapping: per thread 16 halves (2 x uint4) per tile
    const int ar = tid >> 1, ac = (tid & 1) * 16;   // A: 128 rows x 32 cols
    const int br = tid >> 3, bc = (tid & 7) * 16;   // B: 32 rows x 128 cols

    const half* Ag  = Ag_ + (size_t)(rowBase + ar) * K + ac;
    const half* Bg0 = Bhg + (size_t)br * N + colBase + bc;
    const half* Bg1 = Blg + (size_t)br * N + colBase + bc;

    float acc[2][8][4] = {};

    // prologue: stage 0
    {
        half* Ah = sm;
        half* Bh = Ah + A_SZ;
        half* Bl = Bh + B_SZ;
        const uint4* pA = (const uint4*)Ag;
        const uint4* p0 = (const uint4*)Bg0;
        const uint4* p1 = (const uint4*)Bg1;
        *(uint4*)&Ah[ar * ALD + ac]       = pA[0];
        *(uint4*)&Ah[ar * ALD + ac + 8]   = pA[1];
        *(uint4*)&Bh[br * BLD + bc]       = p0[0];
        *(uint4*)&Bh[br * BLD + bc + 8]   = p0[1];
        *(uint4*)&Bl[br * BLD + bc]       = p1[0];
        *(uint4*)&Bl[br * BLD + bc + 8]   = p1[1];
    }
    __syncthreads();

    const int nst = K / BKK;
    for (int s = 0; s < nst; s++) {
        const int cur = s & 1;
        const bool more = (s + 1 < nst);
        uint4 pa[2], pbh[2], pbl[2];
        if (more) {
            const uint4* pA = (const uint4*)(Ag + (s + 1) * BKK);
            const uint4* p0 = (const uint4*)(Bg0 + (size_t)(s + 1) * BKK * N);
            const uint4* p1 = (const uint4*)(Blg + (size_t)((s + 1) * BKK + br) * N + colBase + bc);
            pa[0] = pA[0];  pa[1] = pA[1];
            pbh[0] = p0[0]; pbh[1] = p0[1];
            pbl[0] = p1[0]; pbl[1] = p1[1];
        }

        // compute on stage cur
        {
            half* Ah = sm + (size_t)cur * STAGE_H;
            half* Bh = Ah + A_SZ;
            half* Bl = Bh + B_SZ;
            #pragma unroll
            for (int k16 = 0; k16 < 2; k16++) {
                uint32_t ah[2][4], bh[4][4], bl[4][4];
                const int arow = warp_m * 32 + (lane & 15);
                const int acol = k16 * 16 + (lane >> 4) * 8;
                #pragma unroll
                for (int mi = 0; mi < 2; mi++)
                    LDSM_X4(ah[mi], smem_u32(&Ah[(arow + mi * 16) * ALD + acol]));
                const int brow = k16 * 16 + (lane & 15);
                const int bcol = warp_n * 64 + (lane >> 4) * 8;
                #pragma unroll
                for (int ni = 0; ni < 4; ni++) {
                    LDSM_X4T(bh[ni], smem_u32(&Bh[brow * BLD + bcol + ni * 16]));
                    LDSM_X4T(bl[ni], smem_u32(&Bl[brow * BLD + bcol + ni * 16]));
                }
                #pragma unroll
                for (int mi = 0; mi < 2; mi++)
                    #pragma unroll
                    for (int nj = 0; nj < 8; nj++) {
                        const int ni = nj >> 1, ro = (nj & 1) * 2;
                        MMA16816(acc[mi][nj], ah[mi], bh[ni][ro], bh[ni][ro + 1]);
                        MMA16816(acc[mi][nj], ah[mi], bl[ni][ro], bl[ni][ro + 1]);
                    }
            }
        }

        if (more) {
            half* Ah = sm + (size_t)(cur ^ 1) * STAGE_H;
            half* Bh = Ah + A_SZ;
            half* Bl = Bh + B_SZ;
            *(uint4*)&Ah[ar * ALD + ac]     = pa[0];
            *(uint4*)&Ah[ar * ALD + ac + 8] = pa[1];
            *(uint4*)&Bh[br * BLD + bc]     = pbh[0];
            *(uint4*)&Bh[br * BLD + bc + 8] = pbh[1];
            *(uint4*)&Bl[br * BLD + bc]     = pbl[0];
            *(uint4*)&Bl[br * BLD + bc + 8] = pbl[1];
        }
        __syncthreads();
    }

    // Epilogue
    const int g = lane >> 2;
    const int cc = (lane & 3) * 2;
    #pragma unroll
    for (int mi = 0; mi < 2; mi++) {
        const int r0 = rowBase + warp_m * 32 + mi * 16 + g;
        #pragma unroll
        for (int nj = 0; nj < 8; nj++) {
            const int c0 = colBase + warp_n * 64 + nj * 8 + cc;
            *(float2*)&Cm[(size_t)r0 * N + c0]       = make_float2(acc[mi][nj][0], acc[mi][nj][1]);
            *(float2*)&Cm[(size_t)(r0 + 8) * N + c0] = make_float2(acc[mi][nj][2], acc[mi][nj][3]);
        }
    }
}

// ---------------------------------------------------------------------------
// fp32 -> fp16 bulk convert (8 elems/thread)
// ---------------------------------------------------------------------------
__global__ __launch_bounds__(256)
void cvt_half_kernel(const float* __restrict__ in, half* __restrict__ out, int n) {
    int i = (blockIdx.x * 256 + threadIdx.x) * 8;
    if (i >= n) return;
    float4 v0 = *(const float4*)(in + i);
    float4 v1 = *(const float4*)(in + i + 4);
    half2 h[4];
    h[0] = __floats2half2_rn(v0.x, v0.y);
    h[1] = __floats2half2_rn(v0.z, v0.w);
    h[2] = __floats2half2_rn(v1.x, v1.y);
    h[3] = __floats2half2_rn(v1.z, v1.w);
    *(uint4*)(out + i) = *(uint4*)h;
}

// ---------------------------------------------------------------------------
// fp32 -> (hi, lo) fp16 split (8 elems/thread) — for weights
// ---------------------------------------------------------------------------
__global__ __launch_bounds__(256)
void split_kernel(const float* __restrict__ in, half* __restrict__ hi,
                  half* __restrict__ lo, int n) {
    int i = (blockIdx.x * 256 + threadIdx.x) * 8;
    if (i >= n) return;
    float v[8];
    *(float4*)&v[0] = *(const float4*)(in + i);
    *(float4*)&v[4] = *(const float4*)(in + i + 4);
    half h[8], l[8];
    #pragma unroll
    for (int j = 0; j < 8; j++) {
        h[j] = __float2half_rn(v[j]);
        l[j] = __float2half_rn(v[j] - __half2float(h[j]));
    }
    *(uint4*)(hi + i) = *(uint4*)h;
    *(uint4*)(lo + i) = *(uint4*)l;
}

// ---------------------------------------------------------------------------
// Scan pass 1: per-chunk carry with zero initial state.
// ---------------------------------------------------------------------------
__global__ __launch_bounds__(ST / 2)
void scan1_kernel(const float* __restrict__ A) {
    const int n2 = threadIdx.x;
    const int c = blockIdx.x % NCH;
    const int b = blockIdx.x / NCH;
    const float2 a = ((const float2*)A)[n2];
    const float2* p = (const float2*)(g_uB + ((size_t)(b * LEN + c * CHUNK)) * ST) + n2;
    float2 s = make_float2(0.0f, 0.0f);
    #pragma unroll
    for (int t = 0; t < CHUNK; t++) {
        float2 v = p[(size_t)t * (ST / 2)];
        s.x = fmaf(a.x, s.x, v.x);
        s.y = fmaf(a.y, s.y, v.y);
    }
    ((float2*)g_carry)[(b * NCH + c) * (ST / 2) + n2] = s;
}

// ---------------------------------------------------------------------------
// Scan pass 2: inter-chunk exclusive prefix combine.
// ---------------------------------------------------------------------------
__global__ __launch_bounds__(ST / 2)
void scan2_kernel(const float* __restrict__ A, const float* __restrict__ x0) {
    const int n2 = threadIdx.x;
    const int b = blockIdx.x;
    const float2 a = ((const float2*)A)[n2];
    float2 aL = a;
    #pragma unroll
    for (int i = 0; i < 5; i++) { aL.x *= aL.x; aL.y *= aL.y; }   // a^32
    float2 s = ((const float2*)x0)[b * (ST / 2) + n2];
    #pragma unroll
    for (int c = 0; c < NCH; c++) {
        ((float2*)g_init)[(b * NCH + c) * (ST / 2) + n2] = s;
        float2 cv = ((const float2*)g_carry)[(b * NCH + c) * (ST / 2) + n2];
        s.x = fmaf(aL.x, s.x, cv.x);
        s.y = fmaf(aL.y, s.y, cv.y);
    }
}

// ---------------------------------------------------------------------------
// Scan pass 3: rescan per chunk from true init, write x as fp16 (GEMM2 input).
// ---------------------------------------------------------------------------
__global__ __launch_bounds__(ST / 2)
void scan3_kernel(const float* __restrict__ A, float* __restrict__ xlast) {
    const int n2 = threadIdx.x;
    const int c = blockIdx.x % NCH;
    const int b = blockIdx.x / NCH;
    const float2 a = ((const float2*)A)[n2];
    float2 s = ((const float2*)g_init)[(b * NCH + c) * (ST / 2) + n2];
    const size_t base = ((size_t)(b * LEN + c * CHUNK)) * (ST / 2) + n2;
    const float2* pin = (const float2*)g_uB;
    half2* pout = (half2*)g_xh;
    #pragma unroll
    for (int t = 0; t < CHUNK; t++) {
        float2 v = pin[base + (size_t)t * (ST / 2)];
        s.x = fmaf(a.x, s.x, v.x);
        s.y = fmaf(a.y, s.y, v.y);
        pout[base + (size_t)t * (ST / 2)] = __floats2half2_rn(s.x, s.y);
    }
    if (c == NCH - 1) {
        ((float2*)xlast)[b * (ST / 2) + n2] = s;
    }
}

// ---------------------------------------------------------------------------
// kernel_launch
// Inputs: u [8,4096,512], x0 [8,256], A [256], B [512,256], C [256,512]
// Output: y [8,4096,512] flattened, then x_last [8,256].
// ---------------------------------------------------------------------------
extern "C" void kernel_launch(void* const* d_in, const int* in_sizes, int n_in,
                              void* d_out, int out_size) {
    const float* u  = (const float*)d_in[0];
    const float* x0 = (const float*)d_in[1];
    const float* A  = (const float*)d_in[2];
    const float* B  = (const float*)d_in[3];
    const float* C  = (const float*)d_in[4];

    float* y = (float*)d_out;
    float* xlast = y + (size_t)BATCH * LEN * OUTD;

    float *uB_ptr;
    half *uh_ptr, *xh_ptr, *Bh_ptr, *Bl_ptr, *Ch_ptr, *Cl_ptr;
    cudaGetSymbolAddress((void**)&uB_ptr, g_uB);
    cudaGetSymbolAddress((void**)&uh_ptr, g_uh);
    cudaGetSymbolAddress((void**)&xh_ptr, g_xh);
    cudaGetSymbolAddress((void**)&Bh_ptr, g_Bh);
    cudaGetSymbolAddress((void**)&Bl_ptr, g_Bl);
    cudaGetSymbolAddress((void**)&Ch_ptr, g_Ch);
    cudaGetSymbolAddress((void**)&Cl_ptr, g_Cl);

    cudaFuncSetAttribute(gemm_hmma_h, cudaFuncAttributeMaxDynamicSharedMemorySize, GEMM_SMEM);

    const int M = BATCH * LEN;   // 32768

    // Pre-passes: u -> fp16; split weights once
    {
        int n = M * IND;
        cvt_half_kernel<<<n / (256 * 8), 256>>>(u, uh_ptr, n);
        split_kernel<<<(IND * ST) / (256 * 8), 256>>>(B, Bh_ptr, Bl_ptr, IND * ST);
        split_kernel<<<(ST * OUTD) / (256 * 8), 256>>>(C, Ch_ptr, Cl_ptr, ST * OUTD);
    }

    // GEMM1: uB = uh @ (Bh+Bl)   [32768,512] @ [512,256]
    {
        dim3 grid(ST / BN, M / BM);
        gemm_hmma_h<<<grid, 256, GEMM_SMEM>>>(uh_ptr, Bh_ptr, Bl_ptr, uB_ptr, M, ST, IND);
    }

    // Scan
    scan1_kernel<<<BATCH * NCH, ST / 2>>>(A);
    scan2_kernel<<<BATCH, ST / 2>>>(A, x0);
    scan3_kernel<<<BATCH * NCH, ST / 2>>>(A, xlast);

    // GEMM2: y = xh @ (Ch+Cl)    [32768,256] @ [256,512]
    {
        dim3 grid(OUTD / BN, M / BM);
        gemm_hmma_h<<<grid, 256, GEMM_SMEM>>>(xh_ptr, Ch_ptr, Cl_ptr, y, M, OUTD, ST);
    }
}